// round 15
// baseline (speedup 1.0000x reference)
#include <cuda_runtime.h>
#include <cstdint>

typedef unsigned long long u64;
typedef unsigned int u32;

__device__ __forceinline__ u64 ffma2(u64 a, u64 b, u64 c) {
    u64 d; asm("fma.rn.f32x2 %0, %1, %2, %3;" : "=l"(d) : "l"(a), "l"(b), "l"(c)); return d;
}
__device__ __forceinline__ u64 pack2(float x, float y) {
    u64 r; asm("mov.b64 %0, {%1, %2};" : "=l"(r) : "f"(x), "f"(y)); return r;
}
__device__ __forceinline__ float2 unpack2(u64 v) {
    float2 r; asm("mov.b64 {%0, %1}, %2;" : "=f"(r.x), "=f"(r.y) : "l"(v)); return r;
}
__device__ __forceinline__ float clip1(float v) { return fminf(fmaxf(v, -1.0f), 1.0f); }
__device__ __forceinline__ u64 shfl64(u64 v, int src) {
    u32 lo = (u32)v, hi = (u32)(v >> 32);
    lo = __shfl_sync(0xffffffffu, lo, src);
    hi = __shfl_sync(0xffffffffu, hi, src);
    return ((u64)hi << 32) | (u64)lo;
}
__device__ __forceinline__ void group_bar(int id) {
    asm volatile("bar.sync %0, 128;" :: "r"(id) : "memory");
}
__device__ __forceinline__ u32 cvt_tf32(float x) {
    u32 r; asm("cvt.rna.tf32.f32 %0, %1;" : "=r"(r) : "f"(x)); return r;
}
__device__ __forceinline__ void mma_tf32(float& c0, float& c1, float& c2, float& c3,
                                         u32 a0, u32 a1, u32 a2, u32 a3,
                                         u32 b0, u32 b1) {
    asm volatile(
        "mma.sync.aligned.m16n8k8.row.col.f32.tf32.tf32.f32 "
        "{%0,%1,%2,%3}, {%4,%5,%6,%7}, {%8,%9}, {%0,%1,%2,%3};"
        : "+f"(c0), "+f"(c1), "+f"(c2), "+f"(c3)
        : "r"(a0), "r"(a1), "r"(a2), "r"(a3), "r"(b0), "r"(b1));
}

constexpr int NTHREADS = 512;        // 16 warps = 4 groups x 4 warps
constexpr int NGROUP   = 4;
constexpr int ROWS_G   = 16;
constexpr int ROWS_B   = NGROUP * ROWS_G;   // 64 rows per block-iteration
constexpr int RPW      = 4;          // rows staged per warp
constexpr int GSTRIDE  = 516;        // grid row stride (516 mod 32 = 4 -> conflict-free A loads)
constexpr int VSTRIDE  = 38;
constexpr int H1_G     = 576 * 8;    // h1 floats per group

constexpr int SW2_N = 4 * 8;         // u64
constexpr int E1T_N = 19 * 16;
constexpr int E2T_N = 8 * 16;
constexpr int E3S_N = 8;
constexpr int WU_N  = SW2_N + E1T_N + E2T_N + E3S_N;   // 472 u64
constexpr int W1B_N = 9 * 64;        // floats per split half
constexpr int IN_N  = NGROUP * ROWS_G * GSTRIDE;
constexpr int VB_N  = NGROUP * ROWS_G * VSTRIDE;
constexpr size_t SMEM_BYTES = (size_t)WU_N * 8 +
    (size_t)(2 * W1B_N + IN_N + NGROUP * H1_G + VB_N + 32) * 4;

__global__ __launch_bounds__(NTHREADS, 1)
void lila_kernel(const float* __restrict__ inp,
                 const float* __restrict__ W1, const float* __restrict__ b1,
                 const float* __restrict__ W2, const float* __restrict__ b2,
                 const float* __restrict__ W3, const float* __restrict__ b3,
                 const float* __restrict__ E1, const float* __restrict__ c1,
                 const float* __restrict__ E2, const float* __restrict__ c2,
                 const float* __restrict__ E3, const float* __restrict__ c3,
                 float* __restrict__ out, int B)
{
    extern __shared__ __align__(16) char smem_raw[];
    u64*   SW2 = reinterpret_cast<u64*>(smem_raw);
    u64*   E1T = SW2 + SW2_N;
    u64*   E2T = E1T + E1T_N;
    u64*   E3S = E2T + E2T_N;
    float* W1Bh = reinterpret_cast<float*>(E3S + E3S_N);
    float* W1Bl = W1Bh + W1B_N;
    float* IN   = W1Bl + W1B_N;
    float* H1   = IN + IN_N;
    float* VB   = H1 + NGROUP * H1_G;
    float* c1S  = VB + VB_N;      // 16
    float* c2S  = c1S + 16;       // 16

    const int tid  = threadIdx.x;
    const int lane = tid & 31;
    const int warp = tid >> 5;
    const int g    = warp >> 2;
    const int wsg  = warp & 3;

    // ---- stage epilogue/head weights ----
    for (int i = tid; i < SW2_N; i += NTHREADS) {
        int fp = i >> 3, o = i & 7;
        SW2[i] = pack2(W2[(2 * fp) * 8 + o], W2[(2 * fp + 1) * 8 + o]);
    }
    for (int i = tid; i < E1T_N; i += NTHREADS) {
        int fp = i >> 4, o = i & 15;
        E1T[i] = (fp < 18) ? pack2(E1[(2 * fp) * 16 + o], E1[(2 * fp + 1) * 16 + o])
                           : pack2(E1[36 * 16 + o], 0.0f);
    }
    for (int i = tid; i < E2T_N; i += NTHREADS) {
        int fp = i >> 4, o = i & 15;
        E2T[i] = pack2(E2[(2 * fp) * 16 + o], E2[(2 * fp + 1) * 16 + o]);
    }
    if (tid < 8)  E3S[tid] = pack2(E3[2 * tid], E3[2 * tid + 1]);
    if (tid < 16) { c1S[tid] = c1[tid]; c2S[tid] = c2[tid]; }

    // ---- W1 B-fragments, tf32 hi/lo split ----
    for (int idx = tid; idx < W1B_N; idx += NTHREADS) {
        int c9 = idx >> 6, l2 = idx & 63;
        int l = l2 >> 1, which = l2 & 1;
        int k = (l & 3) + 4 * which;      // K index 0..7
        int n = l >> 2;                   // output 0..7
        float w = (k < 6) ? W1[(c9 * 6 + k) * 8 + n] : 0.0f;
        u32 hi = cvt_tf32(w);
        float lo = w - __uint_as_float(hi);
        W1Bh[idx] = __uint_as_float(hi);
        W1Bl[idx] = __uint_as_float(cvt_tf32(lo));
    }

    // ---- zero grid (pads persist) and VB ----
    for (int i = tid; i < IN_N; i += NTHREADS) IN[i] = 0.0f;
    for (int i = tid; i < VB_N; i += NTHREADS) VB[i] = 0.0f;

    // ---- per-lane register constants ----
    const int r1 = lane >> 2;        // mma row (0..7)
    const int cp = lane & 3;         // mma col-pair
    const float bA = __ldg(b1 + 2 * cp);
    const float bB = __ldg(b1 + 2 * cp + 1);
    float b2f[8];
#pragma unroll
    for (int o = 0; o < 8; o++) b2f[o] = __ldg(b2 + o);
    u64 w3p[4];
#pragma unroll
    for (int q = 0; q < 4; q++) w3p[q] = pack2(__ldg(W3 + 2 * q), __ldg(W3 + 2 * q + 1));
    const float b3s = __ldg(b3);
    const float c3s = __ldg(c3);

    const ulonglong2* SW2v = reinterpret_cast<const ulonglong2*>(SW2);
    const ulonglong2* E1Tv = reinterpret_cast<const ulonglong2*>(E1T);
    const ulonglong2* E2Tv = reinterpret_cast<const ulonglong2*>(E2T);

    float* grp_in = IN + g * (ROWS_G * GSTRIDE);
    float* grp_vb = VB + g * (ROWS_G * VSTRIDE);
    u64*   grp_h1 = reinterpret_cast<u64*>(H1 + g * H1_G);

    // head mapping (warps 0,1 of each group handle 8 rows each)
    const int hr  = lane & 7;
    const int hoq = lane >> 3;
    const float* vrow = grp_vb + (wsg * 8 + hr) * VSTRIDE;

    const int rowsPerIter = gridDim.x * ROWS_B;
    const int barid = g + 1;
    const int rbg0 = blockIdx.x * ROWS_B + g * ROWS_G;
    const int tidg = wsg * 32 + lane;

    __syncthreads();

    for (int rbg = rbg0; rbg < B; rbg += rowsPerIter) {

        group_bar(barid);

        // ---- stage 4 rows per warp: LDG -> tf32 -> STS (fully unrolled, MLP ~48) ----
#pragma unroll
        for (int k = 0; k < RPW; k++) {
            const int rloc = wsg * RPW + k;
            const int row  = rbg + rloc;
            float* dst = grp_in + rloc * GSTRIDE;
            if (row < B) {
                const float* src = inp + (size_t)row * 385;
#pragma unroll
                for (int j = 0; j < 12; j++) {
                    const int i = lane + 32 * j;
                    const int cell = i / 6, f = i - 6 * cell;
                    dst[cell * 8 + f] = __uint_as_float(cvt_tf32(__ldg(src + i)));
                }
                if (lane == 0) grp_vb[rloc * VSTRIDE + 36] = __ldg(src + 384);
            } else {
#pragma unroll
                for (int j = 0; j < 12; j++) {
                    const int i = lane + 32 * j;
                    const int cell = i / 6, f = i - 6 * cell;
                    dst[cell * 8 + f] = 0.0f;
                }
                if (lane == 0) grp_vb[rloc * VSTRIDE + 36] = 0.0f;
            }
        }
        group_bar(barid);

        // ---- B fragments: load once per iteration, reuse across all batches ----
        u64 bh[9], bl[9];
#pragma unroll
        for (int c9 = 0; c9 < 9; c9++) {
            bh[c9] = *reinterpret_cast<const u64*>(W1Bh + c9 * 64 + lane * 2);
            bl[c9] = *reinterpret_cast<const u64*>(W1Bl + c9 * 64 + lane * 2);
        }

        // ---- MMA phase: 3 batches of 3 tiles, 5-column sliding A window ----
        const u32* Ag = reinterpret_cast<const u32*>(grp_in) + r1 * GSTRIDE + cp;
#pragma unroll 1
        for (int t = 0; t < 3; t++) {
            const int bb = wsg + 4 * t;       // half-x-row 0..11
            const int x  = bb >> 1;
            const int y0 = (bb & 1) * 3;

            float hA[3][4], lA[3][4];
#pragma unroll
            for (int j = 0; j < 3; j++)
#pragma unroll
                for (int q = 0; q < 4; q++) { hA[j][q] = 0.0f; lA[j][q] = 0.0f; }

#pragma unroll 1
            for (int ox = 0; ox < 3; ox++) {
                const u32* Ap = Ag + ((x + ox) * 8 + y0) * 8;
                u32 aw[5][4];
#pragma unroll
                for (int c = 0; c < 5; c++) {
                    const u32* P = Ap + c * 8;
                    aw[c][0] = P[0];
                    aw[c][1] = P[8 * GSTRIDE];
                    aw[c][2] = P[4];
                    aw[c][3] = P[8 * GSTRIDE + 4];
                }
#pragma unroll
                for (int oy = 0; oy < 3; oy++) {
                    const int c9 = ox * 3 + oy;
                    const u32 bh0 = (u32)bh[c9], bh1 = (u32)(bh[c9] >> 32);
                    const u32 bl0 = (u32)bl[c9], bl1 = (u32)(bl[c9] >> 32);
#pragma unroll
                    for (int j = 0; j < 3; j++) {
                        const u32* a = aw[j + oy];
                        mma_tf32(hA[j][0], hA[j][1], hA[j][2], hA[j][3],
                                 a[0], a[1], a[2], a[3], bh0, bh1);
                        mma_tf32(lA[j][0], lA[j][1], lA[j][2], lA[j][3],
                                 a[0], a[1], a[2], a[3], bl0, bl1);
                    }
                }
            }

#pragma unroll
            for (int j = 0; j < 3; j++) {
                const int p = x * 6 + y0 + j;
                const float v0 = clip1(hA[j][0] + lA[j][0] + bA);
                const float v1 = clip1(hA[j][1] + lA[j][1] + bB);
                const float v2 = clip1(hA[j][2] + lA[j][2] + bA);
                const float v3 = clip1(hA[j][3] + lA[j][3] + bB);
                const int i0 = p * 16 + r1, i1 = i0 + 8;
                grp_h1[i0 * 4 + (cp ^ ((i0 >> 2) & 3))] = pack2(v0, v1);
                grp_h1[i1 * 4 + (cp ^ ((i1 >> 2) & 3))] = pack2(v2, v3);
            }
        }
        group_bar(barid);

        // ---- epilogue: L2 + L3 per patch-instance (in-lane) ----
#pragma unroll 1
        for (int s = 0; s < 5; s++) {
            const int inst = s * 128 + tidg;
            if (inst < 576) {
                const int pp = inst >> 4, rr = inst & 15;
                const int sw = (inst >> 2) & 3;
                const u64* hb = grp_h1 + inst * 4;
                const u64 q0 = hb[0 ^ sw];
                const u64 q1 = hb[1 ^ sw];
                const u64 q2 = hb[2 ^ sw];
                const u64 q3 = hb[3 ^ sw];

                u64 a2c[8];
#pragma unroll
                for (int o = 0; o < 8; o++) a2c[o] = 0ull;
#pragma unroll
                for (int fp = 0; fp < 4; fp++) {
                    const u64 qf = (fp == 0) ? q0 : (fp == 1) ? q1 : (fp == 2) ? q2 : q3;
                    const ulonglong2 wv0 = SW2v[fp * 4 + 0];
                    const ulonglong2 wv1 = SW2v[fp * 4 + 1];
                    const ulonglong2 wv2 = SW2v[fp * 4 + 2];
                    const ulonglong2 wv3 = SW2v[fp * 4 + 3];
                    a2c[0] = ffma2(qf, wv0.x, a2c[0]);
                    a2c[1] = ffma2(qf, wv0.y, a2c[1]);
                    a2c[2] = ffma2(qf, wv1.x, a2c[2]);
                    a2c[3] = ffma2(qf, wv1.y, a2c[3]);
                    a2c[4] = ffma2(qf, wv2.x, a2c[4]);
                    a2c[5] = ffma2(qf, wv2.y, a2c[5]);
                    a2c[6] = ffma2(qf, wv3.x, a2c[6]);
                    a2c[7] = ffma2(qf, wv3.y, a2c[7]);
                }
                u64 n0, n1, n2, n3;
                {
                    float2 f0 = unpack2(a2c[0]), f1 = unpack2(a2c[1]);
                    float2 f2 = unpack2(a2c[2]), f3 = unpack2(a2c[3]);
                    float2 f4 = unpack2(a2c[4]), f5 = unpack2(a2c[5]);
                    float2 f6 = unpack2(a2c[6]), f7 = unpack2(a2c[7]);
                    n0 = pack2(clip1(f0.x + f0.y + b2f[0]), clip1(f1.x + f1.y + b2f[1]));
                    n1 = pack2(clip1(f2.x + f2.y + b2f[2]), clip1(f3.x + f3.y + b2f[3]));
                    n2 = pack2(clip1(f4.x + f4.y + b2f[4]), clip1(f5.x + f5.y + b2f[5]));
                    n3 = pack2(clip1(f6.x + f6.y + b2f[6]), clip1(f7.x + f7.y + b2f[7]));
                }
                const u64 sacc = ffma2(n0, w3p[0],
                                 ffma2(n1, w3p[1],
                                 ffma2(n2, w3p[2],
                                 ffma2(n3, w3p[3], 0ull))));
                const float2 sf = unpack2(sacc);
                grp_vb[rr * VSTRIDE + pp] = clip1(sf.x + sf.y + b3s);
            }
        }
        group_bar(barid);

        // ---- head: warps 0,1 handle 8 rows each ----
        if (wsg < 2) {
            u64 gacc[4] = {0ull, 0ull, 0ull, 0ull};
#pragma unroll
            for (int fp = 0; fp < 19; fp++) {
                const u64 iv = *reinterpret_cast<const u64*>(vrow + 2 * fp);
                const ulonglong2 wa = E1Tv[fp * 8 + 2 * hoq];
                const ulonglong2 wb = E1Tv[fp * 8 + 2 * hoq + 1];
                gacc[0] = ffma2(iv, wa.x, gacc[0]);
                gacc[1] = ffma2(iv, wa.y, gacc[1]);
                gacc[2] = ffma2(iv, wb.x, gacc[2]);
                gacc[3] = ffma2(iv, wb.y, gacc[3]);
            }
            float gv[4];
#pragma unroll
            for (int k = 0; k < 4; k++) {
                float2 f = unpack2(gacc[k]);
                gv[k] = clip1(f.x + f.y + c1S[4 * hoq + k]);
            }
            u64 q0 = pack2(gv[0], gv[1]), q1 = pack2(gv[2], gv[3]);

            u64 z[8];
#pragma unroll
            for (int cc = 0; cc < 4; cc++) {
                z[2 * cc]     = shfl64(q0, cc * 8 + hr);
                z[2 * cc + 1] = shfl64(q1, cc * 8 + hr);
            }

            u64 d[4] = {0ull, 0ull, 0ull, 0ull};
#pragma unroll
            for (int fp = 0; fp < 8; fp++) {
                const ulonglong2 wa = E2Tv[fp * 8 + 2 * hoq];
                const ulonglong2 wb = E2Tv[fp * 8 + 2 * hoq + 1];
                d[0] = ffma2(z[fp], wa.x, d[0]);
                d[1] = ffma2(z[fp], wa.y, d[1]);
                d[2] = ffma2(z[fp], wb.x, d[2]);
                d[3] = ffma2(z[fp], wb.y, d[3]);
            }
            float dv[4];
#pragma unroll
            for (int k = 0; k < 4; k++) {
                float2 f = unpack2(d[k]);
                dv[k] = clip1(f.x + f.y + c2S[4 * hoq + k]);
            }
            u64 s = ffma2(pack2(dv[0], dv[1]), E3S[2 * hoq],
                    ffma2(pack2(dv[2], dv[3]), E3S[2 * hoq + 1], 0ull));
            float2 sf = unpack2(s);
            float part = sf.x + sf.y;
            part += __shfl_xor_sync(0xffffffffu, part, 8);
            part += __shfl_xor_sync(0xffffffffu, part, 16);
            const int row = rbg + wsg * 8 + hr;
            if (hoq == 0 && row < B) out[row] = clip1(part + c3s);
        }
    }
}

extern "C" void kernel_launch(void* const* d_in, const int* in_sizes, int n_in,
                              void* d_out, int out_size)
{
    const float* inp = (const float*)d_in[0];
    const float* W1  = (const float*)d_in[1];
    const float* b1  = (const float*)d_in[2];
    const float* W2  = (const float*)d_in[3];
    const float* b2  = (const float*)d_in[4];
    const float* W3  = (const float*)d_in[5];
    const float* b3  = (const float*)d_in[6];
    const float* E1  = (const float*)d_in[7];
    const float* c1  = (const float*)d_in[8];
    const float* E2  = (const float*)d_in[9];
    const float* c2  = (const float*)d_in[10];
    const float* E3  = (const float*)d_in[11];
    const float* c3  = (const float*)d_in[12];

    int B = in_sizes[0] / 385;

    cudaFuncSetAttribute(lila_kernel, cudaFuncAttributeMaxDynamicSharedMemorySize,
                         (int)SMEM_BYTES);

    lila_kernel<<<148, NTHREADS, SMEM_BYTES>>>(inp, W1, b1, W2, b2, W3, b3,
                                               E1, c1, E2, c2, E3, c3,
                                               (float*)d_out, B);
}

// round 16
// speedup vs baseline: 1.1749x; 1.1749x over previous
#include <cuda_runtime.h>
#include <cstdint>

typedef unsigned long long u64;
typedef unsigned int u32;

__device__ __forceinline__ u64 ffma2(u64 a, u64 b, u64 c) {
    u64 d; asm("fma.rn.f32x2 %0, %1, %2, %3;" : "=l"(d) : "l"(a), "l"(b), "l"(c)); return d;
}
__device__ __forceinline__ u64 pack2(float x, float y) {
    u64 r; asm("mov.b64 %0, {%1, %2};" : "=l"(r) : "f"(x), "f"(y)); return r;
}
__device__ __forceinline__ float2 unpack2(u64 v) {
    float2 r; asm("mov.b64 {%0, %1}, %2;" : "=f"(r.x), "=f"(r.y) : "l"(v)); return r;
}
__device__ __forceinline__ float clip1(float v) { return fminf(fmaxf(v, -1.0f), 1.0f); }
__device__ __forceinline__ u64 shfl64(u64 v, int src) {
    u32 lo = (u32)v, hi = (u32)(v >> 32);
    lo = __shfl_sync(0xffffffffu, lo, src);
    hi = __shfl_sync(0xffffffffu, hi, src);
    return ((u64)hi << 32) | (u64)lo;
}
__device__ __forceinline__ void group_bar(int id) {
    asm volatile("bar.sync %0, 128;" :: "r"(id) : "memory");
}
__device__ __forceinline__ u32 cvt_tf32(float x) {
    u32 r; asm("cvt.rna.tf32.f32 %0, %1;" : "=r"(r) : "f"(x)); return r;
}
__device__ __forceinline__ void mma_tf32(float& c0, float& c1, float& c2, float& c3,
                                         u32 a0, u32 a1, u32 a2, u32 a3,
                                         u32 b0, u32 b1) {
    asm volatile(
        "mma.sync.aligned.m16n8k8.row.col.f32.tf32.tf32.f32 "
        "{%0,%1,%2,%3}, {%4,%5,%6,%7}, {%8,%9}, {%0,%1,%2,%3};"
        : "+f"(c0), "+f"(c1), "+f"(c2), "+f"(c3)
        : "r"(a0), "r"(a1), "r"(a2), "r"(a3), "r"(b0), "r"(b1));
}

constexpr int NTHREADS = 512;        // 16 warps = 4 groups x 4 warps
constexpr int NGROUP   = 4;
constexpr int ROWS_G   = 16;
constexpr int ROWS_B   = NGROUP * ROWS_G;   // 64 rows per block-iteration
constexpr int RPW      = 4;          // rows staged per warp
constexpr int GSTRIDE  = 516;        // grid row stride (516 mod 32 = 4 -> conflict-free A loads)
constexpr int VSTRIDE  = 38;
constexpr int H1_G     = 576 * 8;    // h1 floats per group

constexpr int SW2_N = 4 * 8;         // u64
constexpr int E1T_N = 19 * 16;
constexpr int E2T_N = 8 * 16;
constexpr int E3S_N = 8;
constexpr int WU_N  = SW2_N + E1T_N + E2T_N + E3S_N;   // 472 u64
constexpr int W1B_N = 9 * 64;        // floats (hi only)
constexpr int IN_N  = NGROUP * ROWS_G * GSTRIDE;
constexpr int VB_N  = NGROUP * ROWS_G * VSTRIDE;
constexpr size_t SMEM_BYTES = (size_t)WU_N * 8 +
    (size_t)(W1B_N + IN_N + NGROUP * H1_G + VB_N + 32) * 4;

__global__ __launch_bounds__(NTHREADS, 1)
void lila_kernel(const float* __restrict__ inp,
                 const float* __restrict__ W1, const float* __restrict__ b1,
                 const float* __restrict__ W2, const float* __restrict__ b2,
                 const float* __restrict__ W3, const float* __restrict__ b3,
                 const float* __restrict__ E1, const float* __restrict__ c1,
                 const float* __restrict__ E2, const float* __restrict__ c2,
                 const float* __restrict__ E3, const float* __restrict__ c3,
                 float* __restrict__ out, int B)
{
    extern __shared__ __align__(16) char smem_raw[];
    u64*   SW2 = reinterpret_cast<u64*>(smem_raw);
    u64*   E1T = SW2 + SW2_N;
    u64*   E2T = E1T + E1T_N;
    u64*   E3S = E2T + E2T_N;
    float* W1Bh = reinterpret_cast<float*>(E3S + E3S_N);
    float* IN   = W1Bh + W1B_N;
    float* H1   = IN + IN_N;
    float* VB   = H1 + NGROUP * H1_G;
    float* c1S  = VB + VB_N;      // 16
    float* c2S  = c1S + 16;       // 16

    const int tid  = threadIdx.x;
    const int lane = tid & 31;
    const int warp = tid >> 5;
    const int g    = warp >> 2;
    const int wsg  = warp & 3;

    // ---- stage epilogue/head weights ----
    for (int i = tid; i < SW2_N; i += NTHREADS) {
        int fp = i >> 3, o = i & 7;
        SW2[i] = pack2(W2[(2 * fp) * 8 + o], W2[(2 * fp + 1) * 8 + o]);
    }
    for (int i = tid; i < E1T_N; i += NTHREADS) {
        int fp = i >> 4, o = i & 15;
        E1T[i] = (fp < 18) ? pack2(E1[(2 * fp) * 16 + o], E1[(2 * fp + 1) * 16 + o])
                           : pack2(E1[36 * 16 + o], 0.0f);
    }
    for (int i = tid; i < E2T_N; i += NTHREADS) {
        int fp = i >> 4, o = i & 15;
        E2T[i] = pack2(E2[(2 * fp) * 16 + o], E2[(2 * fp + 1) * 16 + o]);
    }
    if (tid < 8)  E3S[tid] = pack2(E3[2 * tid], E3[2 * tid + 1]);
    if (tid < 16) { c1S[tid] = c1[tid]; c2S[tid] = c2[tid]; }

    // ---- W1 B-fragments (tf32, single precision level) ----
    for (int idx = tid; idx < W1B_N; idx += NTHREADS) {
        int c9 = idx >> 6, l2 = idx & 63;
        int l = l2 >> 1, which = l2 & 1;
        int k = (l & 3) + 4 * which;      // K index 0..7
        int n = l >> 2;                   // output 0..7
        float w = (k < 6) ? W1[(c9 * 6 + k) * 8 + n] : 0.0f;
        W1Bh[idx] = __uint_as_float(cvt_tf32(w));
    }

    // ---- zero grid (pads persist) and VB ----
    for (int i = tid; i < IN_N; i += NTHREADS) IN[i] = 0.0f;
    for (int i = tid; i < VB_N; i += NTHREADS) VB[i] = 0.0f;

    // ---- per-lane register constants ----
    const int r1 = lane >> 2;        // mma row (0..7)
    const int cp = lane & 3;         // mma col-pair
    const float bA = __ldg(b1 + 2 * cp);
    const float bB = __ldg(b1 + 2 * cp + 1);
    float b2f[8];
#pragma unroll
    for (int o = 0; o < 8; o++) b2f[o] = __ldg(b2 + o);
    u64 w3p[4];
#pragma unroll
    for (int q = 0; q < 4; q++) w3p[q] = pack2(__ldg(W3 + 2 * q), __ldg(W3 + 2 * q + 1));
    const float b3s = __ldg(b3);
    const float c3s = __ldg(c3);

    const ulonglong2* SW2v = reinterpret_cast<const ulonglong2*>(SW2);
    const ulonglong2* E1Tv = reinterpret_cast<const ulonglong2*>(E1T);
    const ulonglong2* E2Tv = reinterpret_cast<const ulonglong2*>(E2T);

    float* grp_in = IN + g * (ROWS_G * GSTRIDE);
    float* grp_vb = VB + g * (ROWS_G * VSTRIDE);
    u64*   grp_h1 = reinterpret_cast<u64*>(H1 + g * H1_G);

    // head mapping (warps 0,1 of each group handle 8 rows each)
    const int hr  = lane & 7;
    const int hoq = lane >> 3;
    const float* vrow = grp_vb + (wsg * 8 + hr) * VSTRIDE;

    const int rowsPerIter = gridDim.x * ROWS_B;
    const int barid = g + 1;
    const int rbg0 = blockIdx.x * ROWS_B + g * ROWS_G;
    const int tidg = wsg * 32 + lane;

    __syncthreads();

    // ---- prologue prefetch ----
    float pf[RPW][12];
    float cv[RPW];
#pragma unroll
    for (int k = 0; k < RPW; k++) {
        const int row = rbg0 + wsg * RPW + k;
        if (row < B) {
            const float* src = inp + (size_t)row * 385;
#pragma unroll
            for (int j = 0; j < 12; j++) pf[k][j] = __ldg(src + lane + 32 * j);
            cv[k] = (lane == 0) ? __ldg(src + 384) : 0.0f;
        } else {
#pragma unroll
            for (int j = 0; j < 12; j++) pf[k][j] = 0.0f;
            cv[k] = 0.0f;
        }
    }

    for (int rbg = rbg0; rbg < B; rbg += rowsPerIter) {

        group_bar(barid);

        // ---- stage grid (tf32-rounded) from prefetch registers ----
#pragma unroll
        for (int k = 0; k < RPW; k++) {
            const int rloc = wsg * RPW + k;
            float* dst = grp_in + rloc * GSTRIDE;
#pragma unroll
            for (int j = 0; j < 12; j++) {
                const int i = lane + 32 * j;
                const int cell = i / 6, f = i - 6 * cell;
                dst[cell * 8 + f] = __uint_as_float(cvt_tf32(pf[k][j]));
            }
            if (lane == 0) grp_vb[rloc * VSTRIDE + 36] = cv[k];
        }
        group_bar(barid);

        // ---- prefetch next iteration (overlaps compute) ----
        const int rbgN = rbg + rowsPerIter;
        if (rbgN < B) {
#pragma unroll
            for (int k = 0; k < RPW; k++) {
                const int row = rbgN + wsg * RPW + k;
                if (row < B) {
                    const float* src = inp + (size_t)row * 385;
#pragma unroll
                    for (int j = 0; j < 12; j++) pf[k][j] = __ldg(src + lane + 32 * j);
                    cv[k] = (lane == 0) ? __ldg(src + 384) : 0.0f;
                } else {
#pragma unroll
                    for (int j = 0; j < 12; j++) pf[k][j] = 0.0f;
                    cv[k] = 0.0f;
                }
            }
        }

        // ---- B fragments: load once per iteration ----
        u64 bh[9];
#pragma unroll
        for (int c9 = 0; c9 < 9; c9++)
            bh[c9] = *reinterpret_cast<const u64*>(W1Bh + c9 * 64 + lane * 2);

        // ---- MMA phase: 3 batches of 3 tiles, 5-column sliding A window ----
        const u32* Ag = reinterpret_cast<const u32*>(grp_in) + r1 * GSTRIDE + cp;
#pragma unroll 1
        for (int t = 0; t < 3; t++) {
            const int bb = wsg + 4 * t;       // half-x-row 0..11
            const int x  = bb >> 1;
            const int y0 = (bb & 1) * 3;

            float acc[3][4];
#pragma unroll
            for (int j = 0; j < 3; j++)
#pragma unroll
                for (int q = 0; q < 4; q++) acc[j][q] = 0.0f;

#pragma unroll 1
            for (int ox = 0; ox < 3; ox++) {
                const u32* Ap = Ag + ((x + ox) * 8 + y0) * 8;
                u32 aw[5][4];
#pragma unroll
                for (int c = 0; c < 5; c++) {
                    const u32* P = Ap + c * 8;
                    aw[c][0] = P[0];
                    aw[c][1] = P[8 * GSTRIDE];
                    aw[c][2] = P[4];
                    aw[c][3] = P[8 * GSTRIDE + 4];
                }
#pragma unroll
                for (int oy = 0; oy < 3; oy++) {
                    const int c9 = ox * 3 + oy;
                    const u32 b0 = (u32)bh[c9], b1v = (u32)(bh[c9] >> 32);
#pragma unroll
                    for (int j = 0; j < 3; j++) {
                        const u32* a = aw[j + oy];
                        mma_tf32(acc[j][0], acc[j][1], acc[j][2], acc[j][3],
                                 a[0], a[1], a[2], a[3], b0, b1v);
                    }
                }
            }

#pragma unroll
            for (int j = 0; j < 3; j++) {
                const int p = x * 6 + y0 + j;
                const float v0 = clip1(acc[j][0] + bA);
                const float v1 = clip1(acc[j][1] + bB);
                const float v2 = clip1(acc[j][2] + bA);
                const float v3 = clip1(acc[j][3] + bB);
                const int i0 = p * 16 + r1, i1 = i0 + 8;
                grp_h1[i0 * 4 + (cp ^ ((i0 >> 2) & 3))] = pack2(v0, v1);
                grp_h1[i1 * 4 + (cp ^ ((i1 >> 2) & 3))] = pack2(v2, v3);
            }
        }
        group_bar(barid);

        // ---- epilogue: L2 + L3 per patch-instance (in-lane) ----
#pragma unroll 1
        for (int s = 0; s < 5; s++) {
            const int inst = s * 128 + tidg;
            if (inst < 576) {
                const int pp = inst >> 4, rr = inst & 15;
                const int sw = (inst >> 2) & 3;
                const u64* hb = grp_h1 + inst * 4;
                const u64 q0 = hb[0 ^ sw];
                const u64 q1 = hb[1 ^ sw];
                const u64 q2 = hb[2 ^ sw];
                const u64 q3 = hb[3 ^ sw];

                u64 a2c[8];
#pragma unroll
                for (int o = 0; o < 8; o++) a2c[o] = 0ull;
#pragma unroll
                for (int fp = 0; fp < 4; fp++) {
                    const u64 qf = (fp == 0) ? q0 : (fp == 1) ? q1 : (fp == 2) ? q2 : q3;
                    const ulonglong2 wv0 = SW2v[fp * 4 + 0];
                    const ulonglong2 wv1 = SW2v[fp * 4 + 1];
                    const ulonglong2 wv2 = SW2v[fp * 4 + 2];
                    const ulonglong2 wv3 = SW2v[fp * 4 + 3];
                    a2c[0] = ffma2(qf, wv0.x, a2c[0]);
                    a2c[1] = ffma2(qf, wv0.y, a2c[1]);
                    a2c[2] = ffma2(qf, wv1.x, a2c[2]);
                    a2c[3] = ffma2(qf, wv1.y, a2c[3]);
                    a2c[4] = ffma2(qf, wv2.x, a2c[4]);
                    a2c[5] = ffma2(qf, wv2.y, a2c[5]);
                    a2c[6] = ffma2(qf, wv3.x, a2c[6]);
                    a2c[7] = ffma2(qf, wv3.y, a2c[7]);
                }
                u64 n0, n1, n2, n3;
                {
                    float2 f0 = unpack2(a2c[0]), f1 = unpack2(a2c[1]);
                    float2 f2 = unpack2(a2c[2]), f3 = unpack2(a2c[3]);
                    float2 f4 = unpack2(a2c[4]), f5 = unpack2(a2c[5]);
                    float2 f6 = unpack2(a2c[6]), f7 = unpack2(a2c[7]);
                    n0 = pack2(clip1(f0.x + f0.y + b2f[0]), clip1(f1.x + f1.y + b2f[1]));
                    n1 = pack2(clip1(f2.x + f2.y + b2f[2]), clip1(f3.x + f3.y + b2f[3]));
                    n2 = pack2(clip1(f4.x + f4.y + b2f[4]), clip1(f5.x + f5.y + b2f[5]));
                    n3 = pack2(clip1(f6.x + f6.y + b2f[6]), clip1(f7.x + f7.y + b2f[7]));
                }
                const u64 sacc = ffma2(n0, w3p[0],
                                 ffma2(n1, w3p[1],
                                 ffma2(n2, w3p[2],
                                 ffma2(n3, w3p[3], 0ull))));
                const float2 sf = unpack2(sacc);
                grp_vb[rr * VSTRIDE + pp] = clip1(sf.x + sf.y + b3s);
            }
        }
        group_bar(barid);

        // ---- head: warps 0,1 handle 8 rows each ----
        if (wsg < 2) {
            u64 gacc[4] = {0ull, 0ull, 0ull, 0ull};
#pragma unroll
            for (int fp = 0; fp < 19; fp++) {
                const u64 iv = *reinterpret_cast<const u64*>(vrow + 2 * fp);
                const ulonglong2 wa = E1Tv[fp * 8 + 2 * hoq];
                const ulonglong2 wb = E1Tv[fp * 8 + 2 * hoq + 1];
                gacc[0] = ffma2(iv, wa.x, gacc[0]);
                gacc[1] = ffma2(iv, wa.y, gacc[1]);
                gacc[2] = ffma2(iv, wb.x, gacc[2]);
                gacc[3] = ffma2(iv, wb.y, gacc[3]);
            }
            float gv[4];
#pragma unroll
            for (int k = 0; k < 4; k++) {
                float2 f = unpack2(gacc[k]);
                gv[k] = clip1(f.x + f.y + c1S[4 * hoq + k]);
            }
            u64 q0 = pack2(gv[0], gv[1]), q1 = pack2(gv[2], gv[3]);

            u64 z[8];
#pragma unroll
            for (int cc = 0; cc < 4; cc++) {
                z[2 * cc]     = shfl64(q0, cc * 8 + hr);
                z[2 * cc + 1] = shfl64(q1, cc * 8 + hr);
            }

            u64 d[4] = {0ull, 0ull, 0ull, 0ull};
#pragma unroll
            for (int fp = 0; fp < 8; fp++) {
                const ulonglong2 wa = E2Tv[fp * 8 + 2 * hoq];
                const ulonglong2 wb = E2Tv[fp * 8 + 2 * hoq + 1];
                d[0] = ffma2(z[fp], wa.x, d[0]);
                d[1] = ffma2(z[fp], wa.y, d[1]);
                d[2] = ffma2(z[fp], wb.x, d[2]);
                d[3] = ffma2(z[fp], wb.y, d[3]);
            }
            float dv[4];
#pragma unroll
            for (int k = 0; k < 4; k++) {
                float2 f = unpack2(d[k]);
                dv[k] = clip1(f.x + f.y + c2S[4 * hoq + k]);
            }
            u64 s = ffma2(pack2(dv[0], dv[1]), E3S[2 * hoq],
                    ffma2(pack2(dv[2], dv[3]), E3S[2 * hoq + 1], 0ull));
            float2 sf = unpack2(s);
            float part = sf.x + sf.y;
            part += __shfl_xor_sync(0xffffffffu, part, 8);
            part += __shfl_xor_sync(0xffffffffu, part, 16);
            const int row = rbg + wsg * 8 + hr;
            if (hoq == 0 && row < B) out[row] = clip1(part + c3s);
        }
    }
}

extern "C" void kernel_launch(void* const* d_in, const int* in_sizes, int n_in,
                              void* d_out, int out_size)
{
    const float* inp = (const float*)d_in[0];
    const float* W1  = (const float*)d_in[1];
    const float* b1  = (const float*)d_in[2];
    const float* W2  = (const float*)d_in[3];
    const float* b2  = (const float*)d_in[4];
    const float* W3  = (const float*)d_in[5];
    const float* b3  = (const float*)d_in[6];
    const float* E1  = (const float*)d_in[7];
    const float* c1  = (const float*)d_in[8];
    const float* E2  = (const float*)d_in[9];
    const float* c2  = (const float*)d_in[10];
    const float* E3  = (const float*)d_in[11];
    const float* c3  = (const float*)d_in[12];

    int B = in_sizes[0] / 385;

    cudaFuncSetAttribute(lila_kernel, cudaFuncAttributeMaxDynamicSharedMemorySize,
                         (int)SMEM_BYTES);

    lila_kernel<<<148, NTHREADS, SMEM_BYTES>>>(inp, W1, b1, W2, b2, W3, b3,
                                               E1, c1, E2, c2, E3, c3,
                                               (float*)d_out, B);
}

// round 17
// speedup vs baseline: 1.2683x; 1.0795x over previous
#include <cuda_runtime.h>
#include <cstdint>

typedef unsigned long long u64;
typedef unsigned int u32;

__device__ __forceinline__ u64 ffma2(u64 a, u64 b, u64 c) {
    u64 d; asm("fma.rn.f32x2 %0, %1, %2, %3;" : "=l"(d) : "l"(a), "l"(b), "l"(c)); return d;
}
__device__ __forceinline__ u64 pack2(float x, float y) {
    u64 r; asm("mov.b64 %0, {%1, %2};" : "=l"(r) : "f"(x), "f"(y)); return r;
}
__device__ __forceinline__ float2 unpack2(u64 v) {
    float2 r; asm("mov.b64 {%0, %1}, %2;" : "=f"(r.x), "=f"(r.y) : "l"(v)); return r;
}
__device__ __forceinline__ float clip1(float v) { return fminf(fmaxf(v, -1.0f), 1.0f); }
__device__ __forceinline__ u64 shfl64(u64 v, int src) {
    u32 lo = (u32)v, hi = (u32)(v >> 32);
    lo = __shfl_sync(0xffffffffu, lo, src);
    hi = __shfl_sync(0xffffffffu, hi, src);
    return ((u64)hi << 32) | (u64)lo;
}
__device__ __forceinline__ u32 cvt_tf32(float x) {
    u32 r; asm("cvt.rna.tf32.f32 %0, %1;" : "=r"(r) : "f"(x)); return r;
}
__device__ __forceinline__ void mma_tf32(float& c0, float& c1, float& c2, float& c3,
                                         u32 a0, u32 a1, u32 a2, u32 a3,
                                         u32 b0, u32 b1) {
    asm volatile(
        "mma.sync.aligned.m16n8k8.row.col.f32.tf32.tf32.f32 "
        "{%0,%1,%2,%3}, {%4,%5,%6,%7}, {%8,%9}, {%0,%1,%2,%3};"
        : "+f"(c0), "+f"(c1), "+f"(c2), "+f"(c3)
        : "r"(a0), "r"(a1), "r"(a2), "r"(a3), "r"(b0), "r"(b1));
}

constexpr int NTHREADS = 128;        // one group per CTA (4 warps)
constexpr int ROWS_G   = 16;         // rows per CTA-iteration
constexpr int RPW      = 4;          // rows staged per warp
constexpr int GSTRIDE  = 516;        // 516 mod 32 = 4 -> conflict-free A loads
constexpr int VSTRIDE  = 38;

constexpr int SW2_N = 4 * 8;         // u64
constexpr int E1T_N = 19 * 16;
constexpr int E2T_N = 8 * 16;
constexpr int E3S_N = 8;
constexpr int WU_N  = SW2_N + E1T_N + E2T_N + E3S_N;   // 472 u64
constexpr int W1B_N = 9 * 64;        // floats
constexpr int IN_N  = ROWS_G * GSTRIDE;     // 8256 floats
constexpr int VB_N  = ROWS_G * VSTRIDE;     // 608 floats
constexpr size_t SMEM_BYTES = (size_t)WU_N * 8 +
    (size_t)(W1B_N + IN_N + VB_N + 32) * 4;   // ~41.7 KB -> 5 CTAs/SM

constexpr int GRID_BLOCKS = 740;     // 5 * 148

__global__ __launch_bounds__(NTHREADS, 5)
void lila_kernel(const float* __restrict__ inp,
                 const float* __restrict__ W1, const float* __restrict__ b1,
                 const float* __restrict__ W2, const float* __restrict__ b2,
                 const float* __restrict__ W3, const float* __restrict__ b3,
                 const float* __restrict__ E1, const float* __restrict__ c1,
                 const float* __restrict__ E2, const float* __restrict__ c2,
                 const float* __restrict__ E3, const float* __restrict__ c3,
                 float* __restrict__ out, int B)
{
    extern __shared__ __align__(16) char smem_raw[];
    u64*   SW2 = reinterpret_cast<u64*>(smem_raw);
    u64*   E1T = SW2 + SW2_N;
    u64*   E2T = E1T + E1T_N;
    u64*   E3S = E2T + E2T_N;
    float* W1Bh = reinterpret_cast<float*>(E3S + E3S_N);
    float* IN   = W1Bh + W1B_N;
    float* VB   = IN + IN_N;
    float* c1S  = VB + VB_N;      // 16
    float* c2S  = c1S + 16;       // 16

    const int tid  = threadIdx.x;
    const int lane = tid & 31;
    const int wsg  = tid >> 5;       // warp 0..3

    // ---- stage epilogue/head weights ----
    for (int i = tid; i < SW2_N; i += NTHREADS) {
        int fp = i >> 3, o = i & 7;
        SW2[i] = pack2(W2[(2 * fp) * 8 + o], W2[(2 * fp + 1) * 8 + o]);
    }
    for (int i = tid; i < E1T_N; i += NTHREADS) {
        int fp = i >> 4, o = i & 15;
        E1T[i] = (fp < 18) ? pack2(E1[(2 * fp) * 16 + o], E1[(2 * fp + 1) * 16 + o])
                           : pack2(E1[36 * 16 + o], 0.0f);
    }
    for (int i = tid; i < E2T_N; i += NTHREADS) {
        int fp = i >> 4, o = i & 15;
        E2T[i] = pack2(E2[(2 * fp) * 16 + o], E2[(2 * fp + 1) * 16 + o]);
    }
    if (tid < 8)  E3S[tid] = pack2(E3[2 * tid], E3[2 * tid + 1]);
    if (tid < 16) { c1S[tid] = c1[tid]; c2S[tid] = c2[tid]; }

    // ---- W1 B-fragments (tf32) ----
    for (int idx = tid; idx < W1B_N; idx += NTHREADS) {
        int c9 = idx >> 6, l2 = idx & 63;
        int l = l2 >> 1, which = l2 & 1;
        int k = (l & 3) + 4 * which;
        int n = l >> 2;
        float w = (k < 6) ? W1[(c9 * 6 + k) * 8 + n] : 0.0f;
        W1Bh[idx] = __uint_as_float(cvt_tf32(w));
    }

    // ---- zero grid (pads persist) and VB ----
    for (int i = tid; i < IN_N; i += NTHREADS) IN[i] = 0.0f;
    for (int i = tid; i < VB_N; i += NTHREADS) VB[i] = 0.0f;

    // ---- per-lane constants ----
    const int r1 = lane >> 2;        // mma row (0..7)
    const int cp = lane & 3;         // mma col-pair
    const int oh = cp & 1;           // L2 output half owned
    const int rh = cp >> 1;          // row half owned (0: r1, 1: r1+8)
    const float bA = __ldg(b1 + 2 * cp);
    const float bB = __ldg(b1 + 2 * cp + 1);
    float b2f[4];
#pragma unroll
    for (int k = 0; k < 4; k++) b2f[k] = __ldg(b2 + 4 * oh + k);
    const u64 w3pa = pack2(__ldg(W3 + 4 * oh + 0), __ldg(W3 + 4 * oh + 1));
    const u64 w3pb = pack2(__ldg(W3 + 4 * oh + 2), __ldg(W3 + 4 * oh + 3));
    const float b3s = __ldg(b3);
    const float c3s = __ldg(c3);

    const ulonglong2* SW2v = reinterpret_cast<const ulonglong2*>(SW2);
    const ulonglong2* E1Tv = reinterpret_cast<const ulonglong2*>(E1T);
    const ulonglong2* E2Tv = reinterpret_cast<const ulonglong2*>(E2T);

    // head mapping (warps 0,1 handle 8 rows each)
    const int hr  = lane & 7;
    const int hoq = lane >> 3;
    const float* vrow = VB + (wsg * 8 + hr) * VSTRIDE;

    const int rowsPerIter = gridDim.x * ROWS_G;
    const int rbg0 = blockIdx.x * ROWS_G;
    const int gbase = (lane & ~3);   // 4*r1, shuffle cluster base

    __syncthreads();

    for (int rbg = rbg0; rbg < B; rbg += rowsPerIter) {

        __syncthreads();   // protect IN/VB vs previous iteration readers

        // ---- stage 4 rows per warp: LDG -> tf32 -> STS (unrolled, MLP ~48) ----
#pragma unroll
        for (int k = 0; k < RPW; k++) {
            const int rloc = wsg * RPW + k;
            const int row  = rbg + rloc;
            float* dst = IN + rloc * GSTRIDE;
            if (row < B) {
                const float* src = inp + (size_t)row * 385;
#pragma unroll
                for (int j = 0; j < 12; j++) {
                    const int i = lane + 32 * j;
                    const int cell = i / 6, f = i - 6 * cell;
                    dst[cell * 8 + f] = __uint_as_float(cvt_tf32(__ldg(src + i)));
                }
                if (lane == 0) VB[rloc * VSTRIDE + 36] = __ldg(src + 384);
            } else {
#pragma unroll
                for (int j = 0; j < 12; j++) {
                    const int i = lane + 32 * j;
                    const int cell = i / 6, f = i - 6 * cell;
                    dst[cell * 8 + f] = 0.0f;
                }
                if (lane == 0) VB[rloc * VSTRIDE + 36] = 0.0f;
            }
        }
        __syncthreads();

        // ---- B fragments ----
        u64 bh[9];
#pragma unroll
        for (int c9 = 0; c9 < 9; c9++)
            bh[c9] = *reinterpret_cast<const u64*>(W1Bh + c9 * 64 + lane * 2);

        // ---- MMA + fused epilogue: 3 batches of 3 patches per warp ----
        const u32* Ag = reinterpret_cast<const u32*>(IN) + r1 * GSTRIDE + cp;
#pragma unroll 1
        for (int t = 0; t < 3; t++) {
            const int bb = wsg + 4 * t;       // half-x-row 0..11
            const int x  = bb >> 1;
            const int y0 = (bb & 1) * 3;

            float acc[3][4];
#pragma unroll
            for (int j = 0; j < 3; j++)
#pragma unroll
                for (int q = 0; q < 4; q++) acc[j][q] = 0.0f;

#pragma unroll 1
            for (int ox = 0; ox < 3; ox++) {
                const u32* Ap = Ag + ((x + ox) * 8 + y0) * 8;
                u32 aw[5][4];
#pragma unroll
                for (int c = 0; c < 5; c++) {
                    const u32* P = Ap + c * 8;
                    aw[c][0] = P[0];
                    aw[c][1] = P[8 * GSTRIDE];
                    aw[c][2] = P[4];
                    aw[c][3] = P[8 * GSTRIDE + 4];
                }
#pragma unroll
                for (int oy = 0; oy < 3; oy++) {
                    const int c9 = ox * 3 + oy;
                    const u32 b0 = (u32)bh[c9], b1v = (u32)(bh[c9] >> 32);
#pragma unroll
                    for (int j = 0; j < 3; j++) {
                        const u32* a = aw[j + oy];
                        mma_tf32(acc[j][0], acc[j][1], acc[j][2], acc[j][3],
                                 a[0], a[1], a[2], a[3], b0, b1v);
                    }
                }
            }

            // fused epilogue per patch: gather h1 via shuffles, L2+L3 in-lane
#pragma unroll
            for (int j = 0; j < 3; j++) {
                const int p = x * 6 + y0 + j;
                const u64 mA = pack2(clip1(acc[j][0] + bA), clip1(acc[j][1] + bB));
                const u64 mB = pack2(clip1(acc[j][2] + bA), clip1(acc[j][3] + bB));

                u64 hk[4];
#pragma unroll
                for (int k = 0; k < 4; k++) {
                    const u64 ra = shfl64(mA, gbase + k);
                    const u64 rb = shfl64(mB, gbase + k);
                    hk[k] = rh ? rb : ra;
                }

                u64 a0 = 0ull, a1 = 0ull, a2 = 0ull, a3 = 0ull;
#pragma unroll
                for (int k = 0; k < 4; k++) {
                    const ulonglong2 wa = SW2v[k * 4 + 2 * oh];
                    const ulonglong2 wb = SW2v[k * 4 + 2 * oh + 1];
                    a0 = ffma2(hk[k], wa.x, a0);
                    a1 = ffma2(hk[k], wa.y, a1);
                    a2 = ffma2(hk[k], wb.x, a2);
                    a3 = ffma2(hk[k], wb.y, a3);
                }
                float2 f0 = unpack2(a0), f1 = unpack2(a1);
                float2 f2 = unpack2(a2), f3 = unpack2(a3);
                const u64 n0 = pack2(clip1(f0.x + f0.y + b2f[0]),
                                     clip1(f1.x + f1.y + b2f[1]));
                const u64 n1 = pack2(clip1(f2.x + f2.y + b2f[2]),
                                     clip1(f3.x + f3.y + b2f[3]));

                const u64 s = ffma2(n0, w3pa, ffma2(n1, w3pb, 0ull));
                const float2 sf = unpack2(s);
                float part = sf.x + sf.y;
                const float tot = part + __shfl_xor_sync(0xffffffffu, part, 1);
                if (oh == 0) {
                    const int row = r1 + 8 * rh;
                    VB[row * VSTRIDE + p] = clip1(tot + b3s);
                }
            }
        }
        __syncthreads();

        // ---- head: warps 0,1 handle 8 rows each; warps 2,3 idle ----
        if (wsg < 2) {
            u64 gacc[4] = {0ull, 0ull, 0ull, 0ull};
#pragma unroll
            for (int fp = 0; fp < 19; fp++) {
                const u64 iv = *reinterpret_cast<const u64*>(vrow + 2 * fp);
                const ulonglong2 wa = E1Tv[fp * 8 + 2 * hoq];
                const ulonglong2 wb = E1Tv[fp * 8 + 2 * hoq + 1];
                gacc[0] = ffma2(iv, wa.x, gacc[0]);
                gacc[1] = ffma2(iv, wa.y, gacc[1]);
                gacc[2] = ffma2(iv, wb.x, gacc[2]);
                gacc[3] = ffma2(iv, wb.y, gacc[3]);
            }
            float gv[4];
#pragma unroll
            for (int k = 0; k < 4; k++) {
                float2 f = unpack2(gacc[k]);
                gv[k] = clip1(f.x + f.y + c1S[4 * hoq + k]);
            }
            u64 q0 = pack2(gv[0], gv[1]), q1 = pack2(gv[2], gv[3]);

            u64 z[8];
#pragma unroll
            for (int cc = 0; cc < 4; cc++) {
                z[2 * cc]     = shfl64(q0, cc * 8 + hr);
                z[2 * cc + 1] = shfl64(q1, cc * 8 + hr);
            }

            u64 d[4] = {0ull, 0ull, 0ull, 0ull};
#pragma unroll
            for (int fp = 0; fp < 8; fp++) {
                const ulonglong2 wa = E2Tv[fp * 8 + 2 * hoq];
                const ulonglong2 wb = E2Tv[fp * 8 + 2 * hoq + 1];
                d[0] = ffma2(z[fp], wa.x, d[0]);
                d[1] = ffma2(z[fp], wa.y, d[1]);
                d[2] = ffma2(z[fp], wb.x, d[2]);
                d[3] = ffma2(z[fp], wb.y, d[3]);
            }
            float dv[4];
#pragma unroll
            for (int k = 0; k < 4; k++) {
                float2 f = unpack2(d[k]);
                dv[k] = clip1(f.x + f.y + c2S[4 * hoq + k]);
            }
            u64 s = ffma2(pack2(dv[0], dv[1]), E3S[2 * hoq],
                    ffma2(pack2(dv[2], dv[3]), E3S[2 * hoq + 1], 0ull));
            float2 sf = unpack2(s);
            float part = sf.x + sf.y;
            part += __shfl_xor_sync(0xffffffffu, part, 8);
            part += __shfl_xor_sync(0xffffffffu, part, 16);
            const int row = rbg + wsg * 8 + hr;
            if (hoq == 0 && row < B) out[row] = clip1(part + c3s);
        }
    }
}

extern "C" void kernel_launch(void* const* d_in, const int* in_sizes, int n_in,
                              void* d_out, int out_size)
{
    const float* inp = (const float*)d_in[0];
    const float* W1  = (const float*)d_in[1];
    const float* b1  = (const float*)d_in[2];
    const float* W2  = (const float*)d_in[3];
    const float* b2  = (const float*)d_in[4];
    const float* W3  = (const float*)d_in[5];
    const float* b3  = (const float*)d_in[6];
    const float* E1  = (const float*)d_in[7];
    const float* c1  = (const float*)d_in[8];
    const float* E2  = (const float*)d_in[9];
    const float* c2  = (const float*)d_in[10];
    const float* E3  = (const float*)d_in[11];
    const float* c3  = (const float*)d_in[12];

    int B = in_sizes[0] / 385;

    cudaFuncSetAttribute(lila_kernel, cudaFuncAttributeMaxDynamicSharedMemorySize,
                         (int)SMEM_BYTES);

    lila_kernel<<<GRID_BLOCKS, NTHREADS, SMEM_BYTES>>>(inp, W1, b1, W2, b2, W3, b3,
                                                       E1, c1, E2, c2, E3, c3,
                                                       (float*)d_out, B);
}